// round 1
// baseline (speedup 1.0000x reference)
#include <cuda_runtime.h>
#include <math.h>

#define Bq    128
#define Mseq  1024
#define Ee    1024
#define Hh    8
#define Dd    128
#define MEMN  40
#define MFULL 1064
#define MIDN  64
#define ALPHA_C 1.3f
#define EPS_C   1e-5f
#define SQRT_D_C    11.313708498984760390f   /* sqrt(128) */
#define SQRT_MEM_C  6.3245553203367586640f   /* sqrt(40)  */

typedef unsigned long long u64;

/* ---------------- scratch (static device memory: allowed) ---------------- */
__device__ float g_q   [Bq * Ee];
__device__ float g_v1  [Bq * Ee];
__device__ float g_K   [(size_t)Bq * Mseq * Ee];   /* 512 MB */
__device__ float g_V2  [(size_t)Bq * Mseq * Ee];   /* 512 MB */
__device__ float g_pool[Bq * Hh * MIDN];
__device__ float g_logits[Bq * Hh * MFULL];

/* ---------------- packed f32x2 helpers (Blackwell FFMA2) ---------------- */
__device__ __forceinline__ u64 pk2(float x, float y) {
    u64 r; asm("mov.b64 %0, {%1, %2};" : "=l"(r) : "f"(x), "f"(y)); return r;
}
__device__ __forceinline__ u64 ff2(u64 a, u64 b, u64 c) {
    u64 d; asm("fma.rn.f32x2 %0, %1, %2, %3;" : "=l"(d) : "l"(a), "l"(b), "l"(c)); return d;
}
__device__ __forceinline__ float2 up2(u64 a) {
    float2 f; asm("mov.b64 {%0, %1}, %2;" : "=f"(f.x), "=f"(f.y) : "l"(a)); return f;
}

__device__ __forceinline__ void st_tile(float (*s)[132], int kl, int r, float4 v) {
    s[kl + 0][r] = v.x; s[kl + 1][r] = v.y; s[kl + 2][r] = v.z; s[kl + 3][r] = v.w;
}

/* =========================================================================
 * proj: C = groupnorm(celu(A @ W^T + bias)) , A:[N,1024] W:[1024,1024]
 * 128x128 tile per block, BK=16, 8x8 microtile, f32x2 packed FFMA.
 * Column tile == one groupnorm group (D=128), so the norm fuses in epilogue.
 * ========================================================================= */
__global__ void __launch_bounds__(256) proj_kernel(
    const float* __restrict__ A, const float* __restrict__ W,
    const float* __restrict__ bias, const float* __restrict__ gamma,
    const float* __restrict__ beta, float* __restrict__ C)
{
    __shared__ float As[2][16][132];
    __shared__ float Bs[2][16][132];

    const int tid = threadIdx.x;
    const int lr  = tid >> 2;      /* loader row 0..63  */
    const int lc  = tid & 3;       /* loader f4  0..3   */
    const int tx  = tid & 15, ty = tid >> 4;
    const int i0  = ty * 8, j0 = tx * 8;

    const size_t rowBase = (size_t)blockIdx.y * 128;
    const size_t colBase = (size_t)blockIdx.x * 128;
    const float4* A4 = (const float4*)(A + rowBase * 1024);
    const float4* W4 = (const float4*)(W + colBase * 1024);

    u64 acc[8][4];
#pragma unroll
    for (int i = 0; i < 8; i++)
#pragma unroll
        for (int j = 0; j < 4; j++) acc[i][j] = 0ULL;

    /* preload tile 0 */
    {
        float4 a0 = A4[lr * 256 + lc];
        float4 a1 = A4[(lr + 64) * 256 + lc];
        float4 b0 = W4[lr * 256 + lc];
        float4 b1 = W4[(lr + 64) * 256 + lc];
        int kl = lc * 4;
        st_tile(As[0], kl, lr,      a0);
        st_tile(As[0], kl, lr + 64, a1);
        st_tile(Bs[0], kl, lr,      b0);
        st_tile(Bs[0], kl, lr + 64, b1);
    }
    __syncthreads();

    for (int t = 0; t < 64; t++) {
        const int cur = t & 1, nxt = cur ^ 1;
        float4 pa0, pa1, pb0, pb1;
        if (t < 63) {
            int f4 = (t + 1) * 4 + lc;
            pa0 = A4[lr * 256 + f4];
            pa1 = A4[(lr + 64) * 256 + f4];
            pb0 = W4[lr * 256 + f4];
            pb1 = W4[(lr + 64) * 256 + f4];
        }
#pragma unroll
        for (int k = 0; k < 16; k++) {
            float4 av0 = *(const float4*)&As[cur][k][i0];
            float4 av1 = *(const float4*)&As[cur][k][i0 + 4];
            ulonglong2 bp0 = *(const ulonglong2*)&Bs[cur][k][j0];
            ulonglong2 bp1 = *(const ulonglong2*)&Bs[cur][k][j0 + 4];
            u64 bv[4] = {bp0.x, bp0.y, bp1.x, bp1.y};
            float av[8] = {av0.x, av0.y, av0.z, av0.w, av1.x, av1.y, av1.z, av1.w};
#pragma unroll
            for (int i = 0; i < 8; i++) {
                u64 ad = pk2(av[i], av[i]);
#pragma unroll
                for (int j = 0; j < 4; j++) acc[i][j] = ff2(ad, bv[j], acc[i][j]);
            }
        }
        if (t < 63) {
            int kl = lc * 4;
            st_tile(As[nxt], kl, lr,      pa0);
            st_tile(As[nxt], kl, lr + 64, pa1);
            st_tile(Bs[nxt], kl, lr,      pb0);
            st_tile(Bs[nxt], kl, lr + 64, pb1);
        }
        __syncthreads();
    }

    /* ------- epilogue: bias + celu + groupnorm (per row over 128 cols) --- */
    float v[8][8];
#pragma unroll
    for (int i = 0; i < 8; i++)
#pragma unroll
        for (int jp = 0; jp < 4; jp++) {
            float2 f = up2(acc[i][jp]);
            v[i][2 * jp] = f.x; v[i][2 * jp + 1] = f.y;
        }

    float bia[8], gam[8], bet[8];
#pragma unroll
    for (int j = 0; j < 8; j++) {
        size_t c = colBase + j0 + j;
        bia[j] = bias[c]; gam[j] = gamma[c]; bet[j] = beta[c];
    }
#pragma unroll
    for (int i = 0; i < 8; i++)
#pragma unroll
        for (int j = 0; j < 8; j++) {
            float x = v[i][j] + bia[j];
            v[i][j] = (x > 0.f) ? x : ALPHA_C * expm1f(x * (1.0f / ALPHA_C));
        }

    /* per-row partial sums; reuse As smem (4224 floats >= 4096) */
    float* rs = &As[0][0][0];
    float* rq = rs + 2048;
#pragma unroll
    for (int i = 0; i < 8; i++) {
        float s = 0.f, q = 0.f;
#pragma unroll
        for (int j = 0; j < 8; j++) { s += v[i][j]; q += v[i][j] * v[i][j]; }
        rs[(i0 + i) * 16 + tx] = s;
        rq[(i0 + i) * 16 + tx] = q;
    }
    __syncthreads();

#pragma unroll
    for (int i = 0; i < 8; i++) {
        int row = i0 + i;
        float S = 0.f, Q = 0.f;
#pragma unroll
        for (int p = 0; p < 16; p++) { S += rs[row * 16 + p]; Q += rq[row * 16 + p]; }
        float mean = S * (1.f / 128.f);
        float var  = Q * (1.f / 128.f) - mean * mean;
        float inv  = rsqrtf(var + EPS_C);
        float o[8];
#pragma unroll
        for (int j = 0; j < 8; j++) o[j] = (v[i][j] - mean) * inv * gam[j] + bet[j];
        float4* dst = (float4*)&C[(rowBase + row) * 1024 + colBase + j0];
        dst[0] = make_float4(o[0], o[1], o[2], o[3]);
        dst[1] = make_float4(o[4], o[5], o[6], o[7]);
    }
}

/* =========================================================================
 * attn_h: per (b,h) block. t[m,d] = q[b,h,d]*k[b,h,m,d]; h = relu(t@Wb^T+bb)
 * emits masked alpha logits (h . Wl + bl) and masked mean pool.
 * ========================================================================= */
__global__ void __launch_bounds__(256) attn_h_kernel(
    const float* __restrict__ mask, const float* __restrict__ mem,
    const float* __restrict__ Wb, const float* __restrict__ bb,
    const float* __restrict__ Wl, const float* __restrict__ bl)
{
    extern __shared__ float sm[];
    float* Wbt  = sm;                     /* [128][64]  transposed Wb */
    float* ts   = sm + 128 * 64;          /* [64][128]  q*k tile      */
    float* lred = ts + 64 * 128;          /* [64][16]                 */
    float* pr   = lred + 64 * 16;         /* [64][16]                 */
    float* msm  = pr + 64 * 16;           /* [1]                      */

    const int bh = blockIdx.x, b = bh >> 3, h = bh & 7;
    const int tid = threadIdx.x;

    /* transpose Wb (64x128 row-major) -> Wbt[d][o] */
    const float4* Wb4 = (const float4*)Wb;
    for (int idx = tid; idx < 2048; idx += 256) {
        int o = idx >> 5, dq = idx & 31;
        float4 w = Wb4[o * 32 + dq];
        Wbt[(dq * 4 + 0) * 64 + o] = w.x;
        Wbt[(dq * 4 + 1) * 64 + o] = w.y;
        Wbt[(dq * 4 + 2) * 64 + o] = w.z;
        Wbt[(dq * 4 + 3) * 64 + o] = w.w;
    }
    if (tid < 32) {
        float s = 0.f;
        for (int m = tid; m < MFULL; m += 32) {
            int mm = (m < Mseq) ? m : (m - Mseq);
            s += mask[b * Mseq + mm];
        }
#pragma unroll
        for (int o = 16; o; o >>= 1) s += __shfl_xor_sync(0xffffffffu, s, o);
        if (tid == 0) msm[0] = s;
    }

    /* loader role */
    const int mr = tid >> 5;
    const int dl = (tid & 31) * 4;
    const float4 qv = *(const float4*)&g_q[b * Ee + h * Dd + dl];

    /* compute role */
    const int o0 = (tid & 15) * 4;
    const int m0 = (tid >> 4) * 4;
    const float4 bbv = *(const float4*)&bb[o0];
    const float4 wlv = *(const float4*)&Wl[o0];
    const float bbf[4] = {bbv.x, bbv.y, bbv.z, bbv.w};
    const float wlf[4] = {wlv.x, wlv.y, wlv.z, wlv.w};
    const float bl0 = bl[0];
    float pools[4] = {0.f, 0.f, 0.f, 0.f};

    __syncthreads();   /* Wbt + msum ready */

    for (int p = 0; p < 17; p++) {
        const int mbase = p * 64;
        /* build t tile */
#pragma unroll
        for (int i = 0; i < 8; i++) {
            int ml = mr + i * 8;
            int mg = mbase + ml;
            float4 kv = make_float4(0.f, 0.f, 0.f, 0.f);
            if (mg < Mseq) {
                kv = *(const float4*)&g_K[((size_t)(b * Mseq + mg)) * Ee + h * Dd + dl];
            } else if (mg < MFULL) {
                float4 mv = *(const float4*)&mem[(size_t)(mg - Mseq) * Ee + h * Dd + dl];
                kv = make_float4(mv.x * SQRT_D_C, mv.y * SQRT_D_C,
                                 mv.z * SQRT_D_C, mv.w * SQRT_D_C);
            }
            *(float4*)&ts[ml * Dd + dl] =
                make_float4(kv.x * qv.x, kv.y * qv.y, kv.z * qv.z, kv.w * qv.w);
        }
        __syncthreads();

        float acc[4][4];
#pragma unroll
        for (int oi = 0; oi < 4; oi++)
#pragma unroll
            for (int mi = 0; mi < 4; mi++) acc[oi][mi] = 0.f;

#pragma unroll 4
        for (int d4 = 0; d4 < 128; d4 += 4) {
            float wf[16], tf[16];
            *(float4*)&wf[0]  = *(const float4*)&Wbt[(d4 + 0) * 64 + o0];
            *(float4*)&wf[4]  = *(const float4*)&Wbt[(d4 + 1) * 64 + o0];
            *(float4*)&wf[8]  = *(const float4*)&Wbt[(d4 + 2) * 64 + o0];
            *(float4*)&wf[12] = *(const float4*)&Wbt[(d4 + 3) * 64 + o0];
            *(float4*)&tf[0]  = *(const float4*)&ts[(m0 + 0) * 128 + d4];
            *(float4*)&tf[4]  = *(const float4*)&ts[(m0 + 1) * 128 + d4];
            *(float4*)&tf[8]  = *(const float4*)&ts[(m0 + 2) * 128 + d4];
            *(float4*)&tf[12] = *(const float4*)&ts[(m0 + 3) * 128 + d4];
#pragma unroll
            for (int j = 0; j < 4; j++)
#pragma unroll
                for (int oi = 0; oi < 4; oi++)
#pragma unroll
                    for (int mi = 0; mi < 4; mi++)
                        acc[oi][mi] += wf[j * 4 + oi] * tf[mi * 4 + j];
        }

        /* relu + logit partials + pool */
        float hr[4][4];
#pragma unroll
        for (int mi = 0; mi < 4; mi++) {
            float s = 0.f;
#pragma unroll
            for (int oi = 0; oi < 4; oi++) {
                float hv = fmaxf(acc[oi][mi] + bbf[oi], 0.f);
                hr[oi][mi] = hv;
                s += hv * wlf[oi];
            }
            lred[(m0 + mi) * 16 + (tid & 15)] = s;
        }
#pragma unroll
        for (int mi = 0; mi < 4; mi++) {
            int mg = mbase + m0 + mi;
            float mv = 0.f;
            if (mg < Mseq)       mv = mask[b * Mseq + mg];
            else if (mg < MFULL) mv = mask[b * Mseq + mg - Mseq];
#pragma unroll
            for (int oi = 0; oi < 4; oi++) pools[oi] += hr[oi][mi] * mv;
        }
        __syncthreads();

        if (tid < 64) {
            int mg = mbase + tid;
            if (mg < MFULL) {
                float s = bl0;
#pragma unroll
                for (int pp = 0; pp < 16; pp++) s += lred[tid * 16 + pp];
                float mv = (mg < Mseq) ? mask[b * Mseq + mg]
                                       : mask[b * Mseq + mg - Mseq];
                g_logits[bh * MFULL + mg] = (mv == 0.f) ? -1e9f : s;
            }
        }
        __syncthreads();
    }

    /* pool reduce */
#pragma unroll
    for (int oi = 0; oi < 4; oi++) pr[(o0 + oi) * 16 + (tid >> 4)] = pools[oi];
    __syncthreads();
    if (tid < 64) {
        float s = 0.f;
#pragma unroll
        for (int pp = 0; pp < 16; pp++) s += pr[tid * 16 + pp];
        g_pool[bh * 64 + tid] = s / msm[0];
    }
}

/* =========================================================================
 * finalize: softmax(logits), alpha_channel = sigmoid(pool@Wl2^T+bl2),
 * v2p = sum_m alpha * v2,  out = v1 * v2p * alpha_channel
 * ========================================================================= */
__global__ void __launch_bounds__(256) finalize_kernel(
    const float* __restrict__ mem, const float* __restrict__ Wl2,
    const float* __restrict__ bl2, float* __restrict__ out)
{
    __shared__ float alpha[MFULL];
    __shared__ float red[256];
    __shared__ float pool_s[64];
    __shared__ float vpart[256];

    const int bh = blockIdx.x, b = bh >> 3, h = bh & 7;
    const int tid = threadIdx.x;

    float mx = -INFINITY;
    for (int m = tid; m < MFULL; m += 256) {
        float l = g_logits[bh * MFULL + m];
        alpha[m] = l;
        mx = fmaxf(mx, l);
    }
    red[tid] = mx;
    __syncthreads();
    for (int s = 128; s > 0; s >>= 1) {
        if (tid < s) red[tid] = fmaxf(red[tid], red[tid + s]);
        __syncthreads();
    }
    mx = red[0];
    __syncthreads();

    float es = 0.f;
    for (int m = tid; m < MFULL; m += 256) {
        float e = expf(alpha[m] - mx);
        alpha[m] = e;
        es += e;
    }
    red[tid] = es;
    if (tid < 64) pool_s[tid] = g_pool[bh * 64 + tid];
    __syncthreads();
    for (int s = 128; s > 0; s >>= 1) {
        if (tid < s) red[tid] += red[tid + s];
        __syncthreads();
    }
    const float sumExp = red[0];

    const int d = tid & 127, half = tid >> 7;
    float acc = 0.f;
    for (int m = half; m < MFULL; m += 2) {
        float a = alpha[m];
        float v;
        if (m < Mseq) v = g_V2[((size_t)(b * Mseq + m)) * Ee + h * Dd + d];
        else          v = SQRT_MEM_C * mem[(size_t)(m - Mseq) * Ee + h * Dd + d];
        acc += a * v;
    }
    vpart[tid] = acc;
    __syncthreads();

    if (tid < 128) {
        float v2p = (vpart[tid] + vpart[tid + 128]) / sumExp;
        float s = bl2[d];
#pragma unroll
        for (int o = 0; o < 64; o++) s += pool_s[o] * Wl2[d * 64 + o];
        float ac = 1.f / (1.f + expf(-s));
        size_t oidx = (size_t)b * Ee + h * Dd + d;
        out[oidx] = g_v1[oidx] * v2p * ac;
    }
}

/* ========================================================================= */
extern "C" void kernel_launch(void* const* d_in, const int* in_sizes, int n_in,
                              void* d_out, int out_size)
{
    const float* query  = (const float*)d_in[0];
    const float* key    = (const float*)d_in[1];
    const float* mask   = (const float*)d_in[2];
    const float* value1 = (const float*)d_in[3];
    const float* value2 = (const float*)d_in[4];
    const float* Wq  = (const float*)d_in[5];  const float* bq  = (const float*)d_in[6];
    const float* gq  = (const float*)d_in[7];  const float* sq  = (const float*)d_in[8];
    const float* Wk  = (const float*)d_in[9];  const float* bk  = (const float*)d_in[10];
    const float* gk  = (const float*)d_in[11]; const float* sk  = (const float*)d_in[12];
    const float* Wv1 = (const float*)d_in[13]; const float* bv1 = (const float*)d_in[14];
    const float* gv1 = (const float*)d_in[15]; const float* sv1 = (const float*)d_in[16];
    const float* Wv2 = (const float*)d_in[17]; const float* bv2 = (const float*)d_in[18];
    const float* gv2 = (const float*)d_in[19]; const float* sv2 = (const float*)d_in[20];
    const float* mem = (const float*)d_in[21];
    const float* Wb  = (const float*)d_in[22]; const float* bb  = (const float*)d_in[23];
    const float* Wl  = (const float*)d_in[24]; const float* bl  = (const float*)d_in[25];
    const float* Wl2 = (const float*)d_in[26]; const float* bl2 = (const float*)d_in[27];
    float* out = (float*)d_out;

    void *pq, *pv1, *pK, *pV2;
    cudaGetSymbolAddress(&pq,  g_q);
    cudaGetSymbolAddress(&pv1, g_v1);
    cudaGetSymbolAddress(&pK,  g_K);
    cudaGetSymbolAddress(&pV2, g_V2);

    const int SMEM2 = (128 * 64 + 64 * 128 + 64 * 16 + 64 * 16 + 8) * 4;
    cudaFuncSetAttribute(attn_h_kernel,
                         cudaFuncAttributeMaxDynamicSharedMemorySize, SMEM2);

    /* small projections: q, v1 (128 rows each) */
    proj_kernel<<<dim3(8, 1), 256>>>(query,  Wq,  bq,  gq,  sq,  (float*)pq);
    proj_kernel<<<dim3(8, 1), 256>>>(value1, Wv1, bv1, gv1, sv1, (float*)pv1);
    /* big projections: k, v2 (131072 rows each) */
    proj_kernel<<<dim3(8, 1024), 256>>>(key,    Wk,  bk,  gk,  sk,  (float*)pK);
    proj_kernel<<<dim3(8, 1024), 256>>>(value2, Wv2, bv2, gv2, sv2, (float*)pV2);

    /* per-(b,h) low-rank scoring: logits + pool */
    attn_h_kernel<<<Bq * Hh, 256, SMEM2>>>(mask, mem, Wb, bb, Wl, bl);

    /* softmax + channel gate + weighted sum + output */
    finalize_kernel<<<Bq * Hh, 256>>>(mem, Wl2, bl2, out);
}